// round 13
// baseline (speedup 1.0000x reference)
#include <cuda_runtime.h>

#define G     8
#define CIN   64
#define COUT  64
#define KS    7
#define PAD   3
#define H     56
#define W     56
#define B     4

#define TH    8
#define TRW   (TH + KS - 1)   // 14
#define SP    68              // smem row stride (floats); 16B multiple

#define PH    62              // padded rows (3 top, 3 bottom)
#define PWS   64              // padded row stride; LEFT PAD = 4

#define NQKV      200704      // qkv threads (1 channel x 4 cols each)
#define NEDGE     114688      // edge halo cells: 8 cols x 56 rows x 256 (b,c)
#define NFULL     24576       // full-row halo float4 cells: 96 x 256

// scratch (allocation-free rule)
__device__ float g_q[B*COUT*H*W];          // interior 56x56, float4 rows
__device__ float g_kp[B*COUT*PH*PWS];      // padded k (halo = bk)
__device__ float g_vp[B*COUT*PH*PWS];      // padded v (halo = bv)

#define EX2F(dst, src) asm("ex2.approx.ftz.f32 %0, %1;" : "=f"(dst) : "f"(src))

// ---------------------------------------------------------------------------
// Kernel 1: fused grouped 1x1 conv, 1 channel x 4 cols per thread (784 blocks
// -> 2x the resident warps of the 2-ch variant; latency-bound kernel needs
// warps). k/v stored into left-pad-4 padded layout with aligned STG.128.
// Halo fill folded in (single predicated round each). log2(e) folded into wq.
// ---------------------------------------------------------------------------
__global__ __launch_bounds__(256)
void qkv_kernel(const float* __restrict__ x,
                const float* __restrict__ wq,
                const float* __restrict__ wk,
                const float* __restrict__ bk,
                const float* __restrict__ wv,
                const float* __restrict__ bv) {
    const float LOG2E = 1.4426950408889634f;
    int idx = blockIdx.x * 256 + threadIdx.x;          // 200,704 threads exact
    int t = idx / 14;
    int j = idx - t*14;
    int h = t % 56;  t /= 56;
    int c = t % 64;
    int b = t / 64;
    int g = c >> 3;

    const float4* xp = (const float4*)x + ((b*CIN + g*8)*H + h)*14 + j;

    float kb = __ldg(&bk[c]);
    float vb = __ldg(&bv[c]);
    float4 aq = make_float4(0.f, 0.f, 0.f, 0.f);
    float4 ak = make_float4(kb, kb, kb, kb);
    float4 av = make_float4(vb, vb, vb, vb);

    #pragma unroll
    for (int i = 0; i < 8; i++) {
        float4 xv  = __ldg(xp + i*784);                 // 784 = H*W/4
        float wqi  = __ldg(&wq[c*8 + i]) * LOG2E;
        float wki  = __ldg(&wk[c*8 + i]);
        float wvi  = __ldg(&wv[c*8 + i]);
        aq.x = fmaf(wqi, xv.x, aq.x); aq.y = fmaf(wqi, xv.y, aq.y);
        aq.z = fmaf(wqi, xv.z, aq.z); aq.w = fmaf(wqi, xv.w, aq.w);
        ak.x = fmaf(wki, xv.x, ak.x); ak.y = fmaf(wki, xv.y, ak.y);
        ak.z = fmaf(wki, xv.z, ak.z); ak.w = fmaf(wki, xv.w, ak.w);
        av.x = fmaf(wvi, xv.x, av.x); av.y = fmaf(wvi, xv.y, av.y);
        av.z = fmaf(wvi, xv.z, av.z); av.w = fmaf(wvi, xv.w, av.w);
    }
    ((float4*)g_q)[idx] = aq;

    // padded aligned k/v stores (row h+3, cols 4j+4 .. 4j+7)
    int pk = ((b*COUT + c)*PH + (h + PAD))*PWS + 4*j + 4;
    *(float4*)(g_kp + pk) = ak;
    *(float4*)(g_vp + pk) = av;

    // ---- halo fill (bias values) ----
    // full halo rows {0,1,2,59,60,61}: 16 float4 per row per (b,c)
    if (idx < NFULL) {
        int bc = idx / 96;
        int local = idx - bc*96;
        int rr = local >> 4;
        int c4 = local & 15;
        int pr = (rr < 3) ? rr : rr + 56;
        int hc = bc & 63, hb = bc >> 6;
        float kbv = __ldg(&bk[hc]);
        float vbv = __ldg(&bv[hc]);
        int gi = ((hb*COUT + hc)*PH + pr)*PWS + 4*c4;
        *(float4*)(g_kp + gi) = make_float4(kbv,kbv,kbv,kbv);
        *(float4*)(g_vp + gi) = make_float4(vbv,vbv,vbv,vbv);
    }
    // edge cols {0..3, 60..63} on interior rows 3..58
    if (idx < NEDGE) {
        int bc = idx / 448;
        int local = idx - bc*448;
        int r3 = local >> 3;
        int ci = local & 7;
        int pr = r3 + 3;
        int pc = (ci < 4) ? ci : ci + 56;
        int hc = bc & 63, hb = bc >> 6;
        int gi = ((hb*COUT + hc)*PH + pr)*PWS + pc;
        g_kp[gi] = __ldg(&bk[hc]);
        g_vp[gi] = __ldg(&bv[hc]);
    }
}

// ---------------------------------------------------------------------------
// Kernel 2: windowed softmax attention, 2 adjacent outputs/thread (R7 body).
// Vector staging with +1-column shuffle shift: smem[s] = gmem[s+1], so the
// compute body keeps the original even-aligned float2 tap mapping.
// ---------------------------------------------------------------------------
__global__ __launch_bounds__(224, 6)
void attn_kernel(const float* __restrict__ rel_x,
                 const float* __restrict__ rel_y,
                 float* __restrict__ out) {
    __shared__ __align__(16) float ks_[TRW*SP];
    __shared__ __align__(16) float vs_[TRW*SP];

    int ht = blockIdx.x;
    int c  = blockIdx.y;
    int b  = blockIdx.z;
    int h0 = ht * TH;
    int tid = threadIdx.x;
    int d = c & 7;

    int r  = tid / 28;
    int wp = tid - r*28;
    int h  = h0 + r;
    int w0 = wp * 2;
    int cbase = (b*COUT + c)*H;

    // prefetch per-thread state (overlaps staging latency)
    float2 qv = ((const float2*)g_q)[(cbase + h)*28 + wp];  // pre-scaled by log2e
    float relv[7];
    #pragma unroll
    for (int jj = 0; jj < 7; jj++)
        relv[jj] = (d < 4) ? __ldg(&rel_x[d*KS + jj]) : __ldg(&rel_y[(d-4)*KS + jj]);

    // staging: load gmem float4 [4c4..4c4+3], store smem [4c4..4c4+3] = gmem[4c4+1..4c4+4]
    // (lane 15/31 wrapped shuffle value lands in smem col 63 — never read)
    {
        int pr = tid >> 4;          // 0..13
        int c4 = tid & 15;          // 0..15
        int gbase = ((b*COUT + c)*PH + (h0 + pr))*PWS + 4*c4;
        float4 k4 = *(const float4*)(g_kp + gbase);
        float4 v4 = *(const float4*)(g_vp + gbase);
        float knx = __shfl_down_sync(0xFFFFFFFFu, k4.x, 1);
        float vnx = __shfl_down_sync(0xFFFFFFFFu, v4.x, 1);
        *(float4*)(ks_ + pr*SP + 4*c4) = make_float4(k4.y, k4.z, k4.w, knx);
        *(float4*)(vs_ + pr*SP + 4*c4) = make_float4(v4.y, v4.z, v4.w, vnx);
    }
    __syncthreads();

    float q0 = qv.x, q1 = qv.y;

    float s0a = 0.f, s0b = 0.f, s1a = 0.f, s1b = 0.f;
    float o0a = 0.f, o0b = 0.f, o1a = 0.f, o1b = 0.f;

    if (d < 4) {
        #pragma unroll
        for (int jy = 0; jy < KS; jy++) {
            const float2* kp = (const float2*)(ks_ + (r + jy)*SP + w0);
            const float2* vp = (const float2*)(vs_ + (r + jy)*SP + w0);
            float2 ka = kp[0], kc = kp[1], ke = kp[2], kg = kp[3];
            float2 va = vp[0], vc = vp[1], ve = vp[2], vg = vp[3];
            float a0 = q0 * relv[jy];
            float a1 = q1 * relv[jy];
            float e;
            EX2F(e, fmaf(q0, ka.x, a0)); s0a += e; o0a = fmaf(e, va.x, o0a);
            EX2F(e, fmaf(q0, ka.y, a0)); s0b += e; o0b = fmaf(e, va.y, o0b);
            EX2F(e, fmaf(q0, kc.x, a0)); s0a += e; o0a = fmaf(e, vc.x, o0a);
            EX2F(e, fmaf(q0, kc.y, a0)); s0b += e; o0b = fmaf(e, vc.y, o0b);
            EX2F(e, fmaf(q0, ke.x, a0)); s0a += e; o0a = fmaf(e, ve.x, o0a);
            EX2F(e, fmaf(q0, ke.y, a0)); s0b += e; o0b = fmaf(e, ve.y, o0b);
            EX2F(e, fmaf(q0, kg.x, a0)); s0a += e; o0a = fmaf(e, vg.x, o0a);
            EX2F(e, fmaf(q1, ka.y, a1)); s1a += e; o1a = fmaf(e, va.y, o1a);
            EX2F(e, fmaf(q1, kc.x, a1)); s1b += e; o1b = fmaf(e, vc.x, o1b);
            EX2F(e, fmaf(q1, kc.y, a1)); s1a += e; o1a = fmaf(e, vc.y, o1a);
            EX2F(e, fmaf(q1, ke.x, a1)); s1b += e; o1b = fmaf(e, ve.x, o1b);
            EX2F(e, fmaf(q1, ke.y, a1)); s1a += e; o1a = fmaf(e, ve.y, o1a);
            EX2F(e, fmaf(q1, kg.x, a1)); s1b += e; o1b = fmaf(e, vg.x, o1b);
            EX2F(e, fmaf(q1, kg.y, a1)); s1a += e; o1a = fmaf(e, vg.y, o1a);
        }
    } else {
        #pragma unroll
        for (int jy = 0; jy < KS; jy++) {
            const float2* kp = (const float2*)(ks_ + (r + jy)*SP + w0);
            const float2* vp = (const float2*)(vs_ + (r + jy)*SP + w0);
            float2 ka = kp[0], kc = kp[1], ke = kp[2], kg = kp[3];
            float2 va = vp[0], vc = vp[1], ve = vp[2], vg = vp[3];
            float e;
            EX2F(e, fmaf(q0, ka.x, q0*relv[0])); s0a += e; o0a = fmaf(e, va.x, o0a);
            EX2F(e, fmaf(q0, ka.y, q0*relv[1])); s0b += e; o0b = fmaf(e, va.y, o0b);
            EX2F(e, fmaf(q0, kc.x, q0*relv[2])); s0a += e; o0a = fmaf(e, vc.x, o0a);
            EX2F(e, fmaf(q0, kc.y, q0*relv[3])); s0b += e; o0b = fmaf(e, vc.y, o0b);
            EX2F(e, fmaf(q0, ke.x, q0*relv[4])); s0a += e; o0a = fmaf(e, ve.x, o0a);
            EX2F(e, fmaf(q0, ke.y, q0*relv[5])); s0b += e; o0b = fmaf(e, ve.y, o0b);
            EX2F(e, fmaf(q0, kg.x, q0*relv[6])); s0a += e; o0a = fmaf(e, vg.x, o0a);
            EX2F(e, fmaf(q1, ka.y, q1*relv[0])); s1a += e; o1a = fmaf(e, va.y, o1a);
            EX2F(e, fmaf(q1, kc.x, q1*relv[1])); s1b += e; o1b = fmaf(e, vc.x, o1b);
            EX2F(e, fmaf(q1, kc.y, q1*relv[2])); s1a += e; o1a = fmaf(e, vc.y, o1a);
            EX2F(e, fmaf(q1, ke.x, q1*relv[3])); s1b += e; o1b = fmaf(e, ve.x, o1b);
            EX2F(e, fmaf(q1, ke.y, q1*relv[4])); s1a += e; o1a = fmaf(e, ve.y, o1a);
            EX2F(e, fmaf(q1, kg.x, q1*relv[5])); s1b += e; o1b = fmaf(e, vg.x, o1b);
            EX2F(e, fmaf(q1, kg.y, q1*relv[6])); s1a += e; o1a = fmaf(e, vg.y, o1a);
        }
    }

    float2 res;
    res.x = __fdividef(o0a + o0b, s0a + s0b);
    res.y = __fdividef(o1a + o1b, s1a + s1b);
    *(float2*)&out[(cbase + h)*W + w0] = res;
}

// ---------------------------------------------------------------------------
extern "C" void kernel_launch(void* const* d_in, const int* in_sizes, int n_in,
                              void* d_out, int out_size) {
    const float* x     = (const float*)d_in[0];
    const float* wq    = (const float*)d_in[1];
    const float* wk    = (const float*)d_in[2];
    const float* bk    = (const float*)d_in[3];
    const float* wv    = (const float*)d_in[4];
    const float* bv    = (const float*)d_in[5];
    const float* rel_x = (const float*)d_in[6];
    const float* rel_y = (const float*)d_in[7];
    float* out = (float*)d_out;

    qkv_kernel<<<784, 256>>>(x, wq, wk, bk, wv, bv);   // conv + halo fill

    dim3 grid(H/TH, COUT, B);   // 1792 blocks
    attn_kernel<<<grid, 224>>>(rel_x, rel_y, out);
}

// round 14
// speedup vs baseline: 1.0887x; 1.0887x over previous
#include <cuda_runtime.h>

#define G     8
#define CIN   64
#define COUT  64
#define KS    7
#define PAD   3
#define H     56
#define W     56
#define B     4

#define TH    8
#define TRW   (TH + KS - 1)   // 14
#define SP    68              // smem row stride (floats); 16B multiple

#define PH    62              // padded rows (3 top, 3 bottom)
#define PWS   64              // padded row stride; LEFT PAD = 4

#define NQKV      100352      // qkv threads
#define NEDGE     114688      // edge halo cells: 8 cols x 56 rows x 256 (b,c)
#define NFULL     24576       // full-row halo float4 cells: 96 x 256

// scratch (allocation-free rule)
__device__ float g_q[B*COUT*H*W];          // interior 56x56, float4 rows
__device__ float g_kp[B*COUT*PH*PWS];      // padded k (halo = bk)
__device__ float g_vp[B*COUT*PH*PWS];      // padded v (halo = bv)

#define EX2F(dst, src) asm("ex2.approx.ftz.f32 %0, %1;" : "=f"(dst) : "f"(src))

// ---------------------------------------------------------------------------
// Kernel 1: fused grouped 1x1 conv (2 channels x 4 cols / thread) + halo fill.
// Weight rows hoisted as 12 front-batched LDG.128 (no in-loop scalar loads).
// k/v -> left-pad-4 padded layout, aligned STG.128. log2(e) folded into q
// at the epilogue.
// ---------------------------------------------------------------------------
__global__ __launch_bounds__(256)
void qkv_kernel(const float* __restrict__ x,
                const float* __restrict__ wq,
                const float* __restrict__ wk,
                const float* __restrict__ bk,
                const float* __restrict__ wv,
                const float* __restrict__ bv) {
    const float LOG2E = 1.4426950408889634f;
    int idx = blockIdx.x * 256 + threadIdx.x;          // 100,352 threads exact
    int t = idx / 14;
    int j = idx - t*14;
    int h = t % 56;  t /= 56;
    int dp = t % 4;  t /= 4;
    int g = t % 8;
    int b = t / 8;
    int c0 = g*8 + dp;
    int c1 = c0 + 4;

    const float4* xp = (const float4*)x + ((b*CIN + g*8)*H + h)*14 + j;

    // front-batched weight rows (2 LDG.128 per row, 6 rows)
    const float4* wq0p = (const float4*)(wq + c0*8);
    const float4* wk0p = (const float4*)(wk + c0*8);
    const float4* wv0p = (const float4*)(wv + c0*8);
    const float4* wq1p = (const float4*)(wq + c1*8);
    const float4* wk1p = (const float4*)(wk + c1*8);
    const float4* wv1p = (const float4*)(wv + c1*8);
    float4 wq0a = __ldg(wq0p), wq0b = __ldg(wq0p + 1);
    float4 wk0a = __ldg(wk0p), wk0b = __ldg(wk0p + 1);
    float4 wv0a = __ldg(wv0p), wv0b = __ldg(wv0p + 1);
    float4 wq1a = __ldg(wq1p), wq1b = __ldg(wq1p + 1);
    float4 wk1a = __ldg(wk1p), wk1b = __ldg(wk1p + 1);
    float4 wv1a = __ldg(wv1p), wv1b = __ldg(wv1p + 1);
    float wQ0[8] = {wq0a.x,wq0a.y,wq0a.z,wq0a.w, wq0b.x,wq0b.y,wq0b.z,wq0b.w};
    float wK0[8] = {wk0a.x,wk0a.y,wk0a.z,wk0a.w, wk0b.x,wk0b.y,wk0b.z,wk0b.w};
    float wV0[8] = {wv0a.x,wv0a.y,wv0a.z,wv0a.w, wv0b.x,wv0b.y,wv0b.z,wv0b.w};
    float wQ1[8] = {wq1a.x,wq1a.y,wq1a.z,wq1a.w, wq1b.x,wq1b.y,wq1b.z,wq1b.w};
    float wK1[8] = {wk1a.x,wk1a.y,wk1a.z,wk1a.w, wk1b.x,wk1b.y,wk1b.z,wk1b.w};
    float wV1[8] = {wv1a.x,wv1a.y,wv1a.z,wv1a.w, wv1b.x,wv1b.y,wv1b.z,wv1b.w};

    float kb0 = __ldg(&bk[c0]), kb1 = __ldg(&bk[c1]);
    float vb0 = __ldg(&bv[c0]), vb1 = __ldg(&bv[c1]);
    float4 aq0 = make_float4(0.f,0.f,0.f,0.f), aq1 = aq0;
    float4 ak0 = make_float4(kb0,kb0,kb0,kb0), ak1 = make_float4(kb1,kb1,kb1,kb1);
    float4 av0 = make_float4(vb0,vb0,vb0,vb0), av1 = make_float4(vb1,vb1,vb1,vb1);

    #pragma unroll
    for (int i = 0; i < 8; i++) {
        float4 xv = __ldg(xp + i*784);
        aq0.x = fmaf(wQ0[i], xv.x, aq0.x); aq0.y = fmaf(wQ0[i], xv.y, aq0.y);
        aq0.z = fmaf(wQ0[i], xv.z, aq0.z); aq0.w = fmaf(wQ0[i], xv.w, aq0.w);
        ak0.x = fmaf(wK0[i], xv.x, ak0.x); ak0.y = fmaf(wK0[i], xv.y, ak0.y);
        ak0.z = fmaf(wK0[i], xv.z, ak0.z); ak0.w = fmaf(wK0[i], xv.w, ak0.w);
        av0.x = fmaf(wV0[i], xv.x, av0.x); av0.y = fmaf(wV0[i], xv.y, av0.y);
        av0.z = fmaf(wV0[i], xv.z, av0.z); av0.w = fmaf(wV0[i], xv.w, av0.w);
        aq1.x = fmaf(wQ1[i], xv.x, aq1.x); aq1.y = fmaf(wQ1[i], xv.y, aq1.y);
        aq1.z = fmaf(wQ1[i], xv.z, aq1.z); aq1.w = fmaf(wQ1[i], xv.w, aq1.w);
        ak1.x = fmaf(wK1[i], xv.x, ak1.x); ak1.y = fmaf(wK1[i], xv.y, ak1.y);
        ak1.z = fmaf(wK1[i], xv.z, ak1.z); ak1.w = fmaf(wK1[i], xv.w, ak1.w);
        av1.x = fmaf(wV1[i], xv.x, av1.x); av1.y = fmaf(wV1[i], xv.y, av1.y);
        av1.z = fmaf(wV1[i], xv.z, av1.z); av1.w = fmaf(wV1[i], xv.w, av1.w);
    }
    // fold log2(e) into q at the epilogue
    aq0.x *= LOG2E; aq0.y *= LOG2E; aq0.z *= LOG2E; aq0.w *= LOG2E;
    aq1.x *= LOG2E; aq1.y *= LOG2E; aq1.z *= LOG2E; aq1.w *= LOG2E;

    int oq0 = ((b*COUT + c0)*H + h)*14 + j;
    int oq1 = ((b*COUT + c1)*H + h)*14 + j;
    ((float4*)g_q)[oq0] = aq0; ((float4*)g_q)[oq1] = aq1;

    // padded aligned k/v stores (row h+3, cols 4j+4 .. 4j+7)
    int pk0 = ((b*COUT + c0)*PH + (h + PAD))*PWS + 4*j + 4;
    int pk1 = ((b*COUT + c1)*PH + (h + PAD))*PWS + 4*j + 4;
    *(float4*)(g_kp + pk0) = ak0;
    *(float4*)(g_vp + pk0) = av0;
    *(float4*)(g_kp + pk1) = ak1;
    *(float4*)(g_vp + pk1) = av1;

    // ---- halo fill ----
    // full halo rows {0,1,2,59,60,61}, 16 float4 each, per (b,c)
    if (idx < NFULL) {
        int bc = idx / 96;
        int local = idx - bc*96;
        int rr = local >> 4;
        int c4 = local & 15;
        int pr = (rr < 3) ? rr : rr + 56;
        int hc = bc & 63, hb = bc >> 6;
        float kbv = __ldg(&bk[hc]);
        float vbv = __ldg(&bv[hc]);
        int gi = ((hb*COUT + hc)*PH + pr)*PWS + 4*c4;
        *(float4*)(g_kp + gi) = make_float4(kbv,kbv,kbv,kbv);
        *(float4*)(g_vp + gi) = make_float4(vbv,vbv,vbv,vbv);
    }
    // edge cols {0..3, 60..63} on interior rows 3..58
    #pragma unroll
    for (int u = 0; u < 2; u++) {
        int cell = idx + u*NQKV;
        if (cell < NEDGE) {
            int bc = cell / 448;
            int local = cell - bc*448;
            int r3 = local >> 3;
            int ci = local & 7;
            int pr = r3 + 3;
            int pc = (ci < 4) ? ci : ci + 56;
            int hc = bc & 63, hb = bc >> 6;
            int gi = ((hb*COUT + hc)*PH + pr)*PWS + pc;
            g_kp[gi] = __ldg(&bk[hc]);
            g_vp[gi] = __ldg(&bv[hc]);
        }
    }
}

// ---------------------------------------------------------------------------
// Kernel 2: windowed softmax attention, 2 adjacent outputs/thread (R7 body).
// Vector staging with +1-column shuffle shift: smem[s] = gmem[s+1], so the
// compute body keeps the original even-aligned float2 tap mapping.
// ---------------------------------------------------------------------------
__global__ __launch_bounds__(224, 6)
void attn_kernel(const float* __restrict__ rel_x,
                 const float* __restrict__ rel_y,
                 float* __restrict__ out) {
    __shared__ __align__(16) float ks_[TRW*SP];
    __shared__ __align__(16) float vs_[TRW*SP];

    int ht = blockIdx.x;
    int c  = blockIdx.y;
    int b  = blockIdx.z;
    int h0 = ht * TH;
    int tid = threadIdx.x;
    int d = c & 7;

    int r  = tid / 28;
    int wp = tid - r*28;
    int h  = h0 + r;
    int w0 = wp * 2;
    int cbase = (b*COUT + c)*H;

    // prefetch per-thread state (overlaps staging latency)
    float2 qv = ((const float2*)g_q)[(cbase + h)*28 + wp];  // pre-scaled by log2e
    float relv[7];
    #pragma unroll
    for (int jj = 0; jj < 7; jj++)
        relv[jj] = (d < 4) ? __ldg(&rel_x[d*KS + jj]) : __ldg(&rel_y[(d-4)*KS + jj]);

    // staging: load gmem float4 [4c4..4c4+3], store smem [4c4..4c4+3] = gmem[4c4+1..4c4+4]
    // (lane 15/31 wrapped shuffle value lands in smem col 63 — never read)
    {
        int pr = tid >> 4;          // 0..13
        int c4 = tid & 15;          // 0..15
        int gbase = ((b*COUT + c)*PH + (h0 + pr))*PWS + 4*c4;
        float4 k4 = *(const float4*)(g_kp + gbase);
        float4 v4 = *(const float4*)(g_vp + gbase);
        float knx = __shfl_down_sync(0xFFFFFFFFu, k4.x, 1);
        float vnx = __shfl_down_sync(0xFFFFFFFFu, v4.x, 1);
        *(float4*)(ks_ + pr*SP + 4*c4) = make_float4(k4.y, k4.z, k4.w, knx);
        *(float4*)(vs_ + pr*SP + 4*c4) = make_float4(v4.y, v4.z, v4.w, vnx);
    }
    __syncthreads();

    float q0 = qv.x, q1 = qv.y;

    float s0a = 0.f, s0b = 0.f, s1a = 0.f, s1b = 0.f;
    float o0a = 0.f, o0b = 0.f, o1a = 0.f, o1b = 0.f;

    if (d < 4) {
        #pragma unroll
        for (int jy = 0; jy < KS; jy++) {
            const float2* kp = (const float2*)(ks_ + (r + jy)*SP + w0);
            const float2* vp = (const float2*)(vs_ + (r + jy)*SP + w0);
            float2 ka = kp[0], kc = kp[1], ke = kp[2], kg = kp[3];
            float2 va = vp[0], vc = vp[1], ve = vp[2], vg = vp[3];
            float a0 = q0 * relv[jy];
            float a1 = q1 * relv[jy];
            float e;
            EX2F(e, fmaf(q0, ka.x, a0)); s0a += e; o0a = fmaf(e, va.x, o0a);
            EX2F(e, fmaf(q0, ka.y, a0)); s0b += e; o0b = fmaf(e, va.y, o0b);
            EX2F(e, fmaf(q0, kc.x, a0)); s0a += e; o0a = fmaf(e, vc.x, o0a);
            EX2F(e, fmaf(q0, kc.y, a0)); s0b += e; o0b = fmaf(e, vc.y, o0b);
            EX2F(e, fmaf(q0, ke.x, a0)); s0a += e; o0a = fmaf(e, ve.x, o0a);
            EX2F(e, fmaf(q0, ke.y, a0)); s0b += e; o0b = fmaf(e, ve.y, o0b);
            EX2F(e, fmaf(q0, kg.x, a0)); s0a += e; o0a = fmaf(e, vg.x, o0a);
            EX2F(e, fmaf(q1, ka.y, a1)); s1a += e; o1a = fmaf(e, va.y, o1a);
            EX2F(e, fmaf(q1, kc.x, a1)); s1b += e; o1b = fmaf(e, vc.x, o1b);
            EX2F(e, fmaf(q1, kc.y, a1)); s1a += e; o1a = fmaf(e, vc.y, o1a);
            EX2F(e, fmaf(q1, ke.x, a1)); s1b += e; o1b = fmaf(e, ve.x, o1b);
            EX2F(e, fmaf(q1, ke.y, a1)); s1a += e; o1a = fmaf(e, ve.y, o1a);
            EX2F(e, fmaf(q1, kg.x, a1)); s1b += e; o1b = fmaf(e, vg.x, o1b);
            EX2F(e, fmaf(q1, kg.y, a1)); s1a += e; o1a = fmaf(e, vg.y, o1a);
        }
    } else {
        #pragma unroll
        for (int jy = 0; jy < KS; jy++) {
            const float2* kp = (const float2*)(ks_ + (r + jy)*SP + w0);
            const float2* vp = (const float2*)(vs_ + (r + jy)*SP + w0);
            float2 ka = kp[0], kc = kp[1], ke = kp[2], kg = kp[3];
            float2 va = vp[0], vc = vp[1], ve = vp[2], vg = vp[3];
            float e;
            EX2F(e, fmaf(q0, ka.x, q0*relv[0])); s0a += e; o0a = fmaf(e, va.x, o0a);
            EX2F(e, fmaf(q0, ka.y, q0*relv[1])); s0b += e; o0b = fmaf(e, va.y, o0b);
            EX2F(e, fmaf(q0, kc.x, q0*relv[2])); s0a += e; o0a = fmaf(e, vc.x, o0a);
            EX2F(e, fmaf(q0, kc.y, q0*relv[3])); s0b += e; o0b = fmaf(e, vc.y, o0b);
            EX2F(e, fmaf(q0, ke.x, q0*relv[4])); s0a += e; o0a = fmaf(e, ve.x, o0a);
            EX2F(e, fmaf(q0, ke.y, q0*relv[5])); s0b += e; o0b = fmaf(e, ve.y, o0b);
            EX2F(e, fmaf(q0, kg.x, q0*relv[6])); s0a += e; o0a = fmaf(e, vg.x, o0a);
            EX2F(e, fmaf(q1, ka.y, q1*relv[0])); s1a += e; o1a = fmaf(e, va.y, o1a);
            EX2F(e, fmaf(q1, kc.x, q1*relv[1])); s1b += e; o1b = fmaf(e, vc.x, o1b);
            EX2F(e, fmaf(q1, kc.y, q1*relv[2])); s1a += e; o1a = fmaf(e, vc.y, o1a);
            EX2F(e, fmaf(q1, ke.x, q1*relv[3])); s1b += e; o1b = fmaf(e, ve.x, o1b);
            EX2F(e, fmaf(q1, ke.y, q1*relv[4])); s1a += e; o1a = fmaf(e, ve.y, o1a);
            EX2F(e, fmaf(q1, kg.x, q1*relv[5])); s1b += e; o1b = fmaf(e, vg.x, o1b);
            EX2F(e, fmaf(q1, kg.y, q1*relv[6])); s1a += e; o1a = fmaf(e, vg.y, o1a);
        }
    }

    float2 res;
    res.x = __fdividef(o0a + o0b, s0a + s0b);
    res.y = __fdividef(o1a + o1b, s1a + s1b);
    *(float2*)&out[(cbase + h)*W + w0] = res;
}

// ---------------------------------------------------------------------------
extern "C" void kernel_launch(void* const* d_in, const int* in_sizes, int n_in,
                              void* d_out, int out_size) {
    const float* x     = (const float*)d_in[0];
    const float* wq    = (const float*)d_in[1];
    const float* wk    = (const float*)d_in[2];
    const float* bk    = (const float*)d_in[3];
    const float* wv    = (const float*)d_in[4];
    const float* bv    = (const float*)d_in[5];
    const float* rel_x = (const float*)d_in[6];
    const float* rel_y = (const float*)d_in[7];
    float* out = (float*)d_out;

    qkv_kernel<<<392, 256>>>(x, wq, wk, bk, wv, bv);   // conv + halo fill

    dim3 grid(H/TH, COUT, B);   // 1792 blocks
    attn_kernel<<<grid, 224>>>(rel_x, rel_y, out);
}

// round 15
// speedup vs baseline: 1.1068x; 1.0167x over previous
#include <cuda_runtime.h>

#define G     8
#define CIN   64
#define COUT  64
#define KS    7
#define PAD   3
#define H     56
#define W     56
#define B     4

#define TH    8
#define TRW   (TH + KS - 1)   // 14
#define SP    68              // smem row stride (floats); 16B multiple

#define PH    62              // padded rows (3 top, 3 bottom)
#define PWS   64              // padded row stride; LEFT PAD = 4

#define NQKV      100352      // qkv threads
#define NEDGE     114688      // edge halo cells: 8 cols x 56 rows x 256 (b,c)
#define NFULL     24576       // full-row halo float4 cells: 96 x 256

// scratch (allocation-free rule)
__device__ float g_q[B*COUT*H*W];          // interior 56x56, float4 rows
__device__ float g_kp[B*COUT*PH*PWS];      // padded k (halo = bk)
__device__ float g_vp[B*COUT*PH*PWS];      // padded v (halo = bv)

#define EX2F(dst, src) asm("ex2.approx.ftz.f32 %0, %1;" : "=f"(dst) : "f"(src))

// ---------------------------------------------------------------------------
// Kernel 1: fused grouped 1x1 conv (2 channels x 4 cols / thread) + halo fill.
// Triggers programmatic launch completion at the head so the dependent attn
// grid gets scheduled and runs its preamble concurrently.
// ---------------------------------------------------------------------------
__global__ __launch_bounds__(256)
void qkv_kernel(const float* __restrict__ x,
                const float* __restrict__ wq,
                const float* __restrict__ wk,
                const float* __restrict__ bk,
                const float* __restrict__ wv,
                const float* __restrict__ bv) {
#if __CUDA_ARCH__ >= 900
    cudaTriggerProgrammaticLaunchCompletion();
#endif
    const float LOG2E = 1.4426950408889634f;
    int idx = blockIdx.x * 256 + threadIdx.x;          // 100,352 threads exact
    int t = idx / 14;
    int j = idx - t*14;
    int h = t % 56;  t /= 56;
    int dp = t % 4;  t /= 4;
    int g = t % 8;
    int b = t / 8;
    int c0 = g*8 + dp;
    int c1 = c0 + 4;

    const float4* xp = (const float4*)x + ((b*CIN + g*8)*H + h)*14 + j;

    // front-batched weight rows (2 LDG.128 per row, 6 rows)
    const float4* wq0p = (const float4*)(wq + c0*8);
    const float4* wk0p = (const float4*)(wk + c0*8);
    const float4* wv0p = (const float4*)(wv + c0*8);
    const float4* wq1p = (const float4*)(wq + c1*8);
    const float4* wk1p = (const float4*)(wk + c1*8);
    const float4* wv1p = (const float4*)(wv + c1*8);
    float4 wq0a = __ldg(wq0p), wq0b = __ldg(wq0p + 1);
    float4 wk0a = __ldg(wk0p), wk0b = __ldg(wk0p + 1);
    float4 wv0a = __ldg(wv0p), wv0b = __ldg(wv0p + 1);
    float4 wq1a = __ldg(wq1p), wq1b = __ldg(wq1p + 1);
    float4 wk1a = __ldg(wk1p), wk1b = __ldg(wk1p + 1);
    float4 wv1a = __ldg(wv1p), wv1b = __ldg(wv1p + 1);
    float wQ0[8] = {wq0a.x,wq0a.y,wq0a.z,wq0a.w, wq0b.x,wq0b.y,wq0b.z,wq0b.w};
    float wK0[8] = {wk0a.x,wk0a.y,wk0a.z,wk0a.w, wk0b.x,wk0b.y,wk0b.z,wk0b.w};
    float wV0[8] = {wv0a.x,wv0a.y,wv0a.z,wv0a.w, wv0b.x,wv0b.y,wv0b.z,wv0b.w};
    float wQ1[8] = {wq1a.x,wq1a.y,wq1a.z,wq1a.w, wq1b.x,wq1b.y,wq1b.z,wq1b.w};
    float wK1[8] = {wk1a.x,wk1a.y,wk1a.z,wk1a.w, wk1b.x,wk1b.y,wk1b.z,wk1b.w};
    float wV1[8] = {wv1a.x,wv1a.y,wv1a.z,wv1a.w, wv1b.x,wv1b.y,wv1b.z,wv1b.w};

    float kb0 = __ldg(&bk[c0]), kb1 = __ldg(&bk[c1]);
    float vb0 = __ldg(&bv[c0]), vb1 = __ldg(&bv[c1]);
    float4 aq0 = make_float4(0.f,0.f,0.f,0.f), aq1 = aq0;
    float4 ak0 = make_float4(kb0,kb0,kb0,kb0), ak1 = make_float4(kb1,kb1,kb1,kb1);
    float4 av0 = make_float4(vb0,vb0,vb0,vb0), av1 = make_float4(vb1,vb1,vb1,vb1);

    #pragma unroll
    for (int i = 0; i < 8; i++) {
        float4 xv = __ldg(xp + i*784);
        aq0.x = fmaf(wQ0[i], xv.x, aq0.x); aq0.y = fmaf(wQ0[i], xv.y, aq0.y);
        aq0.z = fmaf(wQ0[i], xv.z, aq0.z); aq0.w = fmaf(wQ0[i], xv.w, aq0.w);
        ak0.x = fmaf(wK0[i], xv.x, ak0.x); ak0.y = fmaf(wK0[i], xv.y, ak0.y);
        ak0.z = fmaf(wK0[i], xv.z, ak0.z); ak0.w = fmaf(wK0[i], xv.w, ak0.w);
        av0.x = fmaf(wV0[i], xv.x, av0.x); av0.y = fmaf(wV0[i], xv.y, av0.y);
        av0.z = fmaf(wV0[i], xv.z, av0.z); av0.w = fmaf(wV0[i], xv.w, av0.w);
        aq1.x = fmaf(wQ1[i], xv.x, aq1.x); aq1.y = fmaf(wQ1[i], xv.y, aq1.y);
        aq1.z = fmaf(wQ1[i], xv.z, aq1.z); aq1.w = fmaf(wQ1[i], xv.w, aq1.w);
        ak1.x = fmaf(wK1[i], xv.x, ak1.x); ak1.y = fmaf(wK1[i], xv.y, ak1.y);
        ak1.z = fmaf(wK1[i], xv.z, ak1.z); ak1.w = fmaf(wK1[i], xv.w, ak1.w);
        av1.x = fmaf(wV1[i], xv.x, av1.x); av1.y = fmaf(wV1[i], xv.y, av1.y);
        av1.z = fmaf(wV1[i], xv.z, av1.z); av1.w = fmaf(wV1[i], xv.w, av1.w);
    }
    aq0.x *= LOG2E; aq0.y *= LOG2E; aq0.z *= LOG2E; aq0.w *= LOG2E;
    aq1.x *= LOG2E; aq1.y *= LOG2E; aq1.z *= LOG2E; aq1.w *= LOG2E;

    int oq0 = ((b*COUT + c0)*H + h)*14 + j;
    int oq1 = ((b*COUT + c1)*H + h)*14 + j;
    ((float4*)g_q)[oq0] = aq0; ((float4*)g_q)[oq1] = aq1;

    int pk0 = ((b*COUT + c0)*PH + (h + PAD))*PWS + 4*j + 4;
    int pk1 = ((b*COUT + c1)*PH + (h + PAD))*PWS + 4*j + 4;
    *(float4*)(g_kp + pk0) = ak0;
    *(float4*)(g_vp + pk0) = av0;
    *(float4*)(g_kp + pk1) = ak1;
    *(float4*)(g_vp + pk1) = av1;

    // ---- halo fill ----
    if (idx < NFULL) {
        int bc = idx / 96;
        int local = idx - bc*96;
        int rr = local >> 4;
        int c4 = local & 15;
        int pr = (rr < 3) ? rr : rr + 56;
        int hc = bc & 63, hb = bc >> 6;
        float kbv = __ldg(&bk[hc]);
        float vbv = __ldg(&bv[hc]);
        int gi = ((hb*COUT + hc)*PH + pr)*PWS + 4*c4;
        *(float4*)(g_kp + gi) = make_float4(kbv,kbv,kbv,kbv);
        *(float4*)(g_vp + gi) = make_float4(vbv,vbv,vbv,vbv);
    }
    #pragma unroll
    for (int u = 0; u < 2; u++) {
        int cell = idx + u*NQKV;
        if (cell < NEDGE) {
            int bc = cell / 448;
            int local = cell - bc*448;
            int r3 = local >> 3;
            int ci = local & 7;
            int pr = r3 + 3;
            int pc = (ci < 4) ? ci : ci + 56;
            int hc = bc & 63, hb = bc >> 6;
            int gi = ((hb*COUT + hc)*PH + pr)*PWS + pc;
            g_kp[gi] = __ldg(&bk[hc]);
            g_vp[gi] = __ldg(&bv[hc]);
        }
    }
}

// ---------------------------------------------------------------------------
// Kernel 2: windowed softmax attention (R12 body). PDL: preamble (indexing,
// rel loads) runs before cudaGridDependencySynchronize(); all reads of
// qkv-produced buffers come after it.
// ---------------------------------------------------------------------------
__global__ __launch_bounds__(224, 6)
void attn_kernel(const float* __restrict__ rel_x,
                 const float* __restrict__ rel_y,
                 float* __restrict__ out) {
    __shared__ __align__(16) float ks_[TRW*SP];
    __shared__ __align__(16) float vs_[TRW*SP];

    int ht = blockIdx.x;
    int c  = blockIdx.y;
    int b  = blockIdx.z;
    int h0 = ht * TH;
    int tid = threadIdx.x;
    int d = c & 7;

    int r  = tid / 28;
    int wp = tid - r*28;
    int h  = h0 + r;
    int w0 = wp * 2;
    int cbase = (b*COUT + c)*H;

    // preamble: independent of qkv output
    float relv[7];
    #pragma unroll
    for (int jj = 0; jj < 7; jj++)
        relv[jj] = (d < 4) ? __ldg(&rel_x[d*KS + jj]) : __ldg(&rel_y[(d-4)*KS + jj]);
    int pr = tid >> 4;          // 0..13
    int c4 = tid & 15;          // 0..15
    int gbase = ((b*COUT + c)*PH + (h0 + pr))*PWS + 4*c4;

#if __CUDA_ARCH__ >= 900
    cudaGridDependencySynchronize();
#endif

    // prefetch q (depends on qkv)
    float2 qv = ((const float2*)g_q)[(cbase + h)*28 + wp];  // pre-scaled by log2e

    // staging with +1-column shuffle shift: smem[s] = gmem[s+1]
    {
        float4 k4 = *(const float4*)(g_kp + gbase);
        float4 v4 = *(const float4*)(g_vp + gbase);
        float knx = __shfl_down_sync(0xFFFFFFFFu, k4.x, 1);
        float vnx = __shfl_down_sync(0xFFFFFFFFu, v4.x, 1);
        *(float4*)(ks_ + pr*SP + 4*c4) = make_float4(k4.y, k4.z, k4.w, knx);
        *(float4*)(vs_ + pr*SP + 4*c4) = make_float4(v4.y, v4.z, v4.w, vnx);
    }
    __syncthreads();

    float q0 = qv.x, q1 = qv.y;

    float s0a = 0.f, s0b = 0.f, s1a = 0.f, s1b = 0.f;
    float o0a = 0.f, o0b = 0.f, o1a = 0.f, o1b = 0.f;

    if (d < 4) {
        #pragma unroll
        for (int jy = 0; jy < KS; jy++) {
            const float2* kp = (const float2*)(ks_ + (r + jy)*SP + w0);
            const float2* vp = (const float2*)(vs_ + (r + jy)*SP + w0);
            float2 ka = kp[0], kc = kp[1], ke = kp[2], kg = kp[3];
            float2 va = vp[0], vc = vp[1], ve = vp[2], vg = vp[3];
            float a0 = q0 * relv[jy];
            float a1 = q1 * relv[jy];
            float e;
            EX2F(e, fmaf(q0, ka.x, a0)); s0a += e; o0a = fmaf(e, va.x, o0a);
            EX2F(e, fmaf(q0, ka.y, a0)); s0b += e; o0b = fmaf(e, va.y, o0b);
            EX2F(e, fmaf(q0, kc.x, a0)); s0a += e; o0a = fmaf(e, vc.x, o0a);
            EX2F(e, fmaf(q0, kc.y, a0)); s0b += e; o0b = fmaf(e, vc.y, o0b);
            EX2F(e, fmaf(q0, ke.x, a0)); s0a += e; o0a = fmaf(e, ve.x, o0a);
            EX2F(e, fmaf(q0, ke.y, a0)); s0b += e; o0b = fmaf(e, ve.y, o0b);
            EX2F(e, fmaf(q0, kg.x, a0)); s0a += e; o0a = fmaf(e, vg.x, o0a);
            EX2F(e, fmaf(q1, ka.y, a1)); s1a += e; o1a = fmaf(e, va.y, o1a);
            EX2F(e, fmaf(q1, kc.x, a1)); s1b += e; o1b = fmaf(e, vc.x, o1b);
            EX2F(e, fmaf(q1, kc.y, a1)); s1a += e; o1a = fmaf(e, vc.y, o1a);
            EX2F(e, fmaf(q1, ke.x, a1)); s1b += e; o1b = fmaf(e, ve.x, o1b);
            EX2F(e, fmaf(q1, ke.y, a1)); s1a += e; o1a = fmaf(e, ve.y, o1a);
            EX2F(e, fmaf(q1, kg.x, a1)); s1b += e; o1b = fmaf(e, vg.x, o1b);
            EX2F(e, fmaf(q1, kg.y, a1)); s1a += e; o1a = fmaf(e, vg.y, o1a);
        }
    } else {
        #pragma unroll
        for (int jy = 0; jy < KS; jy++) {
            const float2* kp = (const float2*)(ks_ + (r + jy)*SP + w0);
            const float2* vp = (const float2*)(vs_ + (r + jy)*SP + w0);
            float2 ka = kp[0], kc = kp[1], ke = kp[2], kg = kp[3];
            float2 va = vp[0], vc = vp[1], ve = vp[2], vg = vp[3];
            float e;
            EX2F(e, fmaf(q0, ka.x, q0*relv[0])); s0a += e; o0a = fmaf(e, va.x, o0a);
            EX2F(e, fmaf(q0, ka.y, q0*relv[1])); s0b += e; o0b = fmaf(e, va.y, o0b);
            EX2F(e, fmaf(q0, kc.x, q0*relv[2])); s0a += e; o0a = fmaf(e, vc.x, o0a);
            EX2F(e, fmaf(q0, kc.y, q0*relv[3])); s0b += e; o0b = fmaf(e, vc.y, o0b);
            EX2F(e, fmaf(q0, ke.x, q0*relv[4])); s0a += e; o0a = fmaf(e, ve.x, o0a);
            EX2F(e, fmaf(q0, ke.y, q0*relv[5])); s0b += e; o0b = fmaf(e, ve.y, o0b);
            EX2F(e, fmaf(q0, kg.x, q0*relv[6])); s0a += e; o0a = fmaf(e, vg.x, o0a);
            EX2F(e, fmaf(q1, ka.y, q1*relv[0])); s1a += e; o1a = fmaf(e, va.y, o1a);
            EX2F(e, fmaf(q1, kc.x, q1*relv[1])); s1b += e; o1b = fmaf(e, vc.x, o1b);
            EX2F(e, fmaf(q1, kc.y, q1*relv[2])); s1a += e; o1a = fmaf(e, vc.y, o1a);
            EX2F(e, fmaf(q1, ke.x, q1*relv[3])); s1b += e; o1b = fmaf(e, ve.x, o1b);
            EX2F(e, fmaf(q1, ke.y, q1*relv[4])); s1a += e; o1a = fmaf(e, ve.y, o1a);
            EX2F(e, fmaf(q1, kg.x, q1*relv[5])); s1b += e; o1b = fmaf(e, vg.x, o1b);
            EX2F(e, fmaf(q1, kg.y, q1*relv[6])); s1a += e; o1a = fmaf(e, vg.y, o1a);
        }
    }

    float2 res;
    res.x = __fdividef(o0a + o0b, s0a + s0b);
    res.y = __fdividef(o1a + o1b, s1a + s1b);
    *(float2*)&out[(cbase + h)*W + w0] = res;
}

// ---------------------------------------------------------------------------
extern "C" void kernel_launch(void* const* d_in, const int* in_sizes, int n_in,
                              void* d_out, int out_size) {
    const float* x     = (const float*)d_in[0];
    const float* wq    = (const float*)d_in[1];
    const float* wk    = (const float*)d_in[2];
    const float* bk    = (const float*)d_in[3];
    const float* wv    = (const float*)d_in[4];
    const float* bv    = (const float*)d_in[5];
    const float* rel_x = (const float*)d_in[6];
    const float* rel_y = (const float*)d_in[7];
    float* out = (float*)d_out;

    qkv_kernel<<<392, 256>>>(x, wq, wk, bk, wv, bv);   // conv + halo fill

    // attn with programmatic dependent launch (overlap with qkv tail)
    cudaLaunchConfig_t cfg = {};
    cfg.gridDim  = dim3(H/TH, COUT, B);   // 1792 blocks
    cfg.blockDim = dim3(224, 1, 1);
    cfg.dynamicSmemBytes = 0;
    cudaLaunchAttribute attrs[1];
    attrs[0].id = cudaLaunchAttributeProgrammaticStreamSerialization;
    attrs[0].val.programmaticStreamSerializationAllowed = 1;
    cfg.attrs = attrs;
    cfg.numAttrs = 1;
    cudaLaunchKernelEx(&cfg, attn_kernel, rel_x, rel_y, out);
}